// round 15
// baseline (speedup 1.0000x reference)
#include <cuda_runtime.h>
#include <cuda_fp16.h>
#include <cstdint>

#define BB   32
#define CHN  16
#define NN   261
#define MM   256
#define MAT  (MM*MM)
#define NMAT (BB*CHN)

// ---------------- scratch (device globals; no allocs allowed) ----------------
__device__ __align__(256) __half g_Ah  [NMAT * MAT];   // feat fp16 (row-major)
__device__ __align__(256) __half g_B2h [NMAT * MAT];   // B2 row-major fp16
__device__ float g_part[NMAT * 2 * 4];   // [bc][tile 0..1][k: tr2,tr3,tr4,tr5]

// ---------------------------- helpers ---------------------------------------
__device__ __forceinline__ uint32_t smem_u32(const void* p) {
    uint32_t a;
    asm("{ .reg .u64 t; cvta.to.shared.u64 t, %1; cvt.u32.u64 %0, t; }" : "=r"(a) : "l"(p));
    return a;
}
#define CP16(dst, src) asm volatile("cp.async.cg.shared.global [%0], [%1], 16;" :: "r"((uint32_t)(dst)), "l"(src))
#define CP_COMMIT()    asm volatile("cp.async.commit_group;" ::: "memory")
#define CP_WAIT(n)     asm volatile("cp.async.wait_group %0;" :: "n"(n) : "memory")

#define MMA_F16(d, a, b) \
    asm volatile("mma.sync.aligned.m16n8k16.row.col.f32.f16.f16.f32 " \
        "{%0,%1,%2,%3},{%4,%5,%6,%7},{%8,%9},{%0,%1,%2,%3};" \
        : "+f"((d)[0]), "+f"((d)[1]), "+f"((d)[2]), "+f"((d)[3]) \
        : "r"((a)[0]), "r"((a)[1]), "r"((a)[2]), "r"((a)[3]), "r"((b)[0]), "r"((b)[1]))

#define LDSM4(r, addr) \
    asm volatile("ldmatrix.sync.aligned.m8n8.x4.shared.b16 {%0,%1,%2,%3}, [%4];" \
        : "=r"((r)[0]), "=r"((r)[1]), "=r"((r)[2]), "=r"((r)[3]) : "r"(addr))

#define LDSM4T(r, addr) \
    asm volatile("ldmatrix.sync.aligned.m8n8.x4.trans.shared.b16 {%0,%1,%2,%3}, [%4];" \
        : "=r"((r)[0]), "=r"((r)[1]), "=r"((r)[2]), "=r"((r)[3]) : "r"(addr))

// ---------------------------------------------------------------------------
// Conv via implicit GEMM on tensor cores (unchanged from R14).
// ---------------------------------------------------------------------------
#define CV_PADK 56
#define CV_P    0
#define CV_XS   57344
#define CV_WS   59040
#define CV_BS   60832
#define CV_SMEM 60896
#define CV_OS   18

__global__ void __launch_bounds__(256, 2) conv_kernel(const float* __restrict__ x,
                                                      const float* __restrict__ w,
                                                      const float* __restrict__ bias) {
    extern __shared__ char sm[];
    __half* P   = (__half*)(sm + CV_P);
    __half* xs  = (__half*)(sm + CV_XS);    // [21][40]
    __half* ws  = (__half*)(sm + CV_WS);    // [16][56]
    float*  bs  = (float*)(sm + CV_BS);
    const uint32_t sbase = smem_u32(sm);
    const int b  = blockIdx.z;
    const int by = blockIdx.y;
    const int bx = blockIdx.x;
    const int tid = threadIdx.x;
    const int lane = tid & 31, wp = tid >> 5;

    for (int i = tid; i < 21 * 37; i += 256) {
        int r = i / 37, c = i % 37;
        xs[r * 40 + c] = __float2half_rn(x[b * NN * NN + (by * 16 + r) * NN + bx * 32 + c]);
    }
    for (int i = tid; i < 16 * CV_PADK; i += 256) {
        int k = i % CV_PADK;
        ws[i] = (k < 36) ? __float2half_rn(w[(i / CV_PADK) * 36 + k]) : __float2half_rn(0.f);
    }
    if (tid < 16) bs[tid] = bias[tid];
    __syncthreads();

#pragma unroll
    for (int it = 0; it < 2; it++) {
        int o = it * 256 + tid;
        int r = o >> 5, c = o & 31;
        __half* Po = P + o * CV_PADK;
#pragma unroll
        for (int p = 0; p < 6; p++) {
            const __half* xr = xs + (r + p) * 40 + c;
#pragma unroll
            for (int j = 0; j < 3; j++)
                *(__half2*)&Po[p * 6 + 2 * j] = __halves2half2(xr[2 * j], xr[2 * j + 1]);
        }
#pragma unroll
        for (int j = 0; j < 6; j++)
            *(__half2*)&Po[36 + 2 * j] = __halves2half2(__float2half_rn(0.f), __float2half_rn(0.f));
    }
    __syncthreads();

    uint32_t bq[3][4];
    {
        uint32_t wOff = sbase + CV_WS
                      + (uint32_t)(((lane & 7) + ((lane >> 4) << 3)) * (CV_PADK * 2)
                      + ((lane >> 3) & 1) * 16);
#pragma unroll
        for (int k = 0; k < 3; k++) LDSM4(bq[k], wOff + (uint32_t)(k * 32));
    }

    const uint32_t aOff = sbase + CV_P
                        + (uint32_t)(((lane & 15) * CV_PADK + ((lane >> 4) << 3)) * 2)
                        + (uint32_t)(wp * 64 * CV_PADK * 2);
    float acc[4][2][4];
#pragma unroll
    for (int mi = 0; mi < 4; mi++)
#pragma unroll
        for (int ni = 0; ni < 2; ni++)
#pragma unroll
            for (int e = 0; e < 4; e++) acc[mi][ni][e] = 0.f;

#pragma unroll
    for (int mi = 0; mi < 4; mi++) {
#pragma unroll
        for (int k = 0; k < 3; k++) {
            uint32_t af[4];
            LDSM4(af, aOff + (uint32_t)(mi * 16 * CV_PADK * 2 + k * 32));
            MMA_F16(acc[mi][0], af, &bq[k][0]);
            MMA_F16(acc[mi][1], af, &bq[k][2]);
        }
    }
    __syncthreads();

    __half* outs = (__half*)(sm + CV_P);    // [512][CV_OS]
    const int fr = lane >> 2, fc = (lane & 3) * 2;
#pragma unroll
    for (int mi = 0; mi < 4; mi++) {
        int o = wp * 64 + mi * 16 + fr;
#pragma unroll
        for (int ni = 0; ni < 2; ni++) {
            int ch = ni * 8 + fc;
            float b0 = bs[ch], b1 = bs[ch + 1];
            *(__half2*)&outs[o * CV_OS + ch] =
                __halves2half2(__float2half_rn(acc[mi][ni][0] + b0),
                               __float2half_rn(acc[mi][ni][1] + b1));
            *(__half2*)&outs[(o + 8) * CV_OS + ch] =
                __halves2half2(__float2half_rn(acc[mi][ni][2] + b0),
                               __float2half_rn(acc[mi][ni][3] + b1));
        }
    }
    __syncthreads();

#pragma unroll
    for (int it = 0; it < 4; it++) {
        int u = it * 256 + tid;
        int ch = (u >> 2) & 15;
        int chunk = (u & 3) + ((u >> 6) << 2);
        int o0 = chunk * 8;
        int r = o0 >> 5, c0 = o0 & 31;
        __half tmp[8];
#pragma unroll
        for (int i = 0; i < 8; i++) tmp[i] = outs[(o0 + i) * CV_OS + ch];
        size_t dst = (size_t)(b * CHN + ch) * MAT + (size_t)(by * 16 + r) * MM + bx * 32 + c0;
        *(uint4*)&g_Ah[dst] = *(uint4*)tmp;
    }
}

// ---------------------------------------------------------------------------
// fp16 mma.sync GEMM, 128x256 tile (full N), 512 threads, BK=32, 3-stage ring.
// IS2=0: C = A@A, warps 2x8 over 128x256. Fragment-direct B2 stores + tr2.
// IS2=1: D = C^T (operand swap), warps 4x4 over 256x128. tr3/tr4/tr5 direct.
// ---------------------------------------------------------------------------
#define PADK    40                     // A tile halves/row (32+8); 80B stride
#define PADN    264                    // B tile halves/row (256+8); 528B stride
#define OFFB    10240u
#define SB      27136u                 // 10240 + 32*528
#define GEMM_SMEM 81408                // 3 stages

__device__ __forceinline__ void load_stage(uint32_t st,
        const __half* __restrict__ Ah, const __half* __restrict__ Bsrc,
        int kb, int tid) {
#pragma unroll
    for (int it = 0; it < 3; ++it) {
        int u = it * 512 + tid;          // 0..1535
        if (u < 512) {
            int rowA = u >> 2, segA = u & 3;
            uint32_t da = (uint32_t)(rowA * (PADK * 2) + segA * 16);
            CP16(st + da, Ah + rowA * MM + kb * 32 + segA * 8);
        } else {
            int v = u - 512;
            int rowB = v >> 5, segB = v & 31;
            uint32_t db = (uint32_t)(rowB * (PADN * 2) + segB * 16);
            CP16(st + OFFB + db, Bsrc + (size_t)(kb * 32 + rowB) * MM + segB * 8);
        }
    }
}

template <bool IS2>
__global__ void __launch_bounds__(512, 1) gemm_kernel() {
    extern __shared__ char sm[];
    const uint32_t sbase = smem_u32(sm);
    const int tid  = threadIdx.x;
    const int lane = tid & 31;
    const int w    = tid >> 5;                    // 0..15
    const int wm   = IS2 ? (w >> 2) : (w >> 3);   // g1: 0..1, g2: 0..3
    const int wn   = IS2 ? (w & 3)  : (w & 7);    // g1: 0..7, g2: 0..3
    const int bc   = blockIdx.z;
    const int row0 = blockIdx.y * 128;
    const size_t mbase = (size_t)bc * MAT;

    const __half* Ah = g_Ah + mbase + (size_t)row0 * MM;
    const __half* Bsrc = (IS2 ? g_B2h : g_Ah) + mbase;

    uint32_t aOff, bOff;
    if (!IS2) {
        // A-op: A rows (m), non-trans. B-op: full-width k-major tile, trans.
        aOff = (uint32_t)(((lane & 15) * PADK + ((lane >> 4) << 3)) * 2)
             + (uint32_t)(wm * 64 * PADK * 2);
        bOff = OFFB
             + (uint32_t)(((lane & 7) + ((lane >> 3) & 1) * 8) * (PADN * 2)
             + (wn * 32 + (lane >> 4) * 8) * 2);
    } else {
        // A-op: B2 k-major tile, trans (m = j over 256). B-op: A rows, non-trans (n = i over 128).
        aOff = OFFB
             + (uint32_t)(((lane & 7) + ((lane >> 4) << 3)) * (PADN * 2)
             + (wm * 64 + ((lane >> 3) & 1) * 8) * 2);
        bOff = (uint32_t)((wn * 32 + (lane & 7) + ((lane >> 4) << 3)) * (PADK * 2)
             + ((lane >> 3) & 1) * 16);
    }

    float acc[4][4][4];
#pragma unroll
    for (int mi = 0; mi < 4; mi++)
#pragma unroll
        for (int ni = 0; ni < 4; ni++)
#pragma unroll
            for (int e = 0; e < 4; e++) acc[mi][ni][e] = 0.f;

    load_stage(sbase + 0 * SB, Ah, Bsrc, 0, tid); CP_COMMIT();
    load_stage(sbase + 1 * SB, Ah, Bsrc, 1, tid); CP_COMMIT();

    for (int kb = 0; kb < 8; ++kb) {
        if (kb < 7) { CP_WAIT(1); } else { CP_WAIT(0); }
        __syncthreads();
        if (kb + 2 < 8) {
            load_stage(sbase + (uint32_t)((kb + 2) % 3) * SB, Ah, Bsrc, kb + 2, tid);
            CP_COMMIT();
        }

        const uint32_t st = sbase + (uint32_t)(kb % 3) * SB;

#pragma unroll
        for (int ks = 0; ks < 2; ++ks) {
            uint32_t af[4][4], bq[2][4];
            if (!IS2) {
#pragma unroll
                for (int mi = 0; mi < 4; mi++)
                    LDSM4(af[mi], st + aOff + (uint32_t)(mi * 16 * PADK * 2 + ks * 32));
#pragma unroll
                for (int q = 0; q < 2; q++)
                    LDSM4T(bq[q], st + bOff + (uint32_t)(ks * 16 * PADN * 2 + q * 16 * 2));
            } else {
#pragma unroll
                for (int mi = 0; mi < 4; mi++)
                    LDSM4T(af[mi], st + aOff + (uint32_t)(ks * 16 * PADN * 2 + mi * 16 * 2));
#pragma unroll
                for (int q = 0; q < 2; q++)
                    LDSM4(bq[q], st + bOff + (uint32_t)(q * 16 * PADK * 2 + ks * 32));
            }
#pragma unroll
            for (int mi = 0; mi < 4; mi++)
#pragma unroll
                for (int ni = 0; ni < 4; ni++)
                    MMA_F16(acc[mi][ni], af[mi], &bq[ni >> 1][(ni & 1) * 2]);
        }
    }
    __syncthreads();

    // ---------------- epilogue: straight from fragments ----------------
    float p0 = 0.f, p2 = 0.f, p3 = 0.f;
    const int fr = lane >> 2;
    const int fc = (lane & 3) * 2;

    if (!IS2) {
#pragma unroll
        for (int mi = 0; mi < 4; mi++)
#pragma unroll
            for (int ni = 0; ni < 4; ni++) {
                int r = row0 + wm * 64 + mi * 16 + fr;   // global row
                int c = wn * 32 + ni * 8 + fc;           // global col (col0 = 0)
                float a0 = acc[mi][ni][0], a1 = acc[mi][ni][1];
                float a2 = acc[mi][ni][2], a3 = acc[mi][ni][3];
                size_t o = mbase + (size_t)r * MM + c;
                *(__half2*)&g_B2h[o] = __halves2half2(__float2half_rn(a0), __float2half_rn(a1));
                *(__half2*)&g_B2h[o + 8 * MM] = __halves2half2(__float2half_rn(a2), __float2half_rn(a3));
                if (r == c)         p0 += a0;
                if (r == c + 1)     p0 += a1;
                if (r + 8 == c)     p0 += a2;
                if (r + 8 == c + 1) p0 += a3;
            }
    } else {
#pragma unroll
        for (int mi = 0; mi < 4; mi++)
#pragma unroll
            for (int ni = 0; ni < 4; ni++) {
                int j = wm * 64 + mi * 16 + fr;          // global col of C (0..255)
                int i = row0 + wn * 32 + ni * 8 + fc;    // global row of C
                float a0 = acc[mi][ni][0], a1 = acc[mi][ni][1];
                float a2 = acc[mi][ni][2], a3 = acc[mi][ni][3];
                size_t o = mbase + (size_t)j * MM + i;
                float2 av1 = __half22float2(*(const __half2*)&g_Ah[o]);
                float2 bv1 = __half22float2(*(const __half2*)&g_B2h[o]);
                float2 av2 = __half22float2(*(const __half2*)&g_Ah[o + 8 * MM]);
                float2 bv2 = __half22float2(*(const __half2*)&g_B2h[o + 8 * MM]);
                p2 += a0 * av1.x + a1 * av1.y + a2 * av2.x + a3 * av2.y;  // tr(A^4)
                p3 += a0 * bv1.x + a1 * bv1.y + a2 * bv2.x + a3 * bv2.y;  // tr(A^5)
                if (j == i)         p0 += a0;   // tr(A^3)
                if (j == i + 1)     p0 += a1;
                if (j + 8 == i)     p0 += a2;
                if (j + 8 == i + 1) p0 += a3;
            }
    }

#pragma unroll
    for (int off = 16; off; off >>= 1) {
        p0 += __shfl_down_sync(0xFFFFFFFFu, p0, off);
        p2 += __shfl_down_sync(0xFFFFFFFFu, p2, off);
        p3 += __shfl_down_sync(0xFFFFFFFFu, p3, off);
    }
    float* red = (float*)sm;
    __syncthreads();
    if (lane == 0) {
        red[w * 3 + 0] = p0; red[w * 3 + 1] = p2; red[w * 3 + 2] = p3;
    }
    __syncthreads();
    if (tid == 0) {
        float s0 = 0.f, s2 = 0.f, s3 = 0.f;
        for (int q = 0; q < 16; q++) {
            s0 += red[q * 3]; s2 += red[q * 3 + 1]; s3 += red[q * 3 + 2];
        }
        int slot = (bc * 2 + (int)blockIdx.y) * 4;
        if (!IS2) g_part[slot + 0] = s0;
        else { g_part[slot + 1] = s0; g_part[slot + 2] = s2; g_part[slot + 3] = s3; }
    }
}

// ---------------------------------------------------------------------------
// Combine: out[b] = sum coef[c,i,j] * tr_{i+2}^(j+1) / 65536^(i+j+1)
// ---------------------------------------------------------------------------
__global__ void __launch_bounds__(512) final_kernel(const float* __restrict__ coef,
                                                    float* __restrict__ out) {
    int t = threadIdx.x;
    int b = t >> 4, c = t & 15;
    int bc = b * CHN + c;
    double tr[4];
#pragma unroll
    for (int k = 0; k < 4; k++) {
        float s = g_part[(bc * 2 + 0) * 4 + k] + g_part[(bc * 2 + 1) * 4 + k];
        tr[k] = (double)s;
    }
    double sum = 0.0;
#pragma unroll
    for (int i = 0; i < 4; i++) {
        double p = tr[i];
        double tp = p;
#pragma unroll
        for (int j = 0; j < 4; j++) {
            double v = ldexp(tp, -16 * (i + j + 1));
            sum += (double)coef[c * 16 + i * 4 + j] * v;
            tp *= p;
        }
    }
#pragma unroll
    for (int off = 8; off; off >>= 1)
        sum += __shfl_down_sync(0xFFFFFFFFu, sum, off, 16);
    if (c == 0) out[b] = (float)sum;
}

extern "C" void kernel_launch(void* const* d_in, const int* in_sizes, int n_in,
                              void* d_out, int out_size) {
    const float* x    = (const float*)d_in[0];
    const float* w    = (const float*)d_in[1];
    const float* bias = (const float*)d_in[2];
    const float* coef = (const float*)d_in[3];
    float* out = (float*)d_out;

    cudaFuncSetAttribute(conv_kernel, cudaFuncAttributeMaxDynamicSharedMemorySize, CV_SMEM);
    cudaFuncSetAttribute(gemm_kernel<false>, cudaFuncAttributeMaxDynamicSharedMemorySize, GEMM_SMEM);
    cudaFuncSetAttribute(gemm_kernel<true>,  cudaFuncAttributeMaxDynamicSharedMemorySize, GEMM_SMEM);

    conv_kernel<<<dim3(8, 16, BB), 256, CV_SMEM>>>(x, w, bias);
    gemm_kernel<false><<<dim3(1, 2, NMAT), 512, GEMM_SMEM>>>();
    gemm_kernel<true> <<<dim3(1, 2, NMAT), 512, GEMM_SMEM>>>();
    final_kernel<<<1, 512>>>(coef, out);
}

// round 16
// speedup vs baseline: 1.0623x; 1.0623x over previous
#include <cuda_runtime.h>
#include <cuda_fp16.h>
#include <cstdint>

#define BB   32
#define CHN  16
#define NN   261
#define MM   256
#define MAT  (MM*MM)
#define NMAT (BB*CHN)

// ---------------- scratch (device globals; no allocs allowed) ----------------
__device__ __align__(256) __half g_Ah  [NMAT * MAT];   // feat fp16 (row-major)
__device__ __align__(256) __half g_B2h [NMAT * MAT];   // B2 row-major fp16
__device__ float g_part[NMAT * 4 * 4];   // [bc][tile 2x2][k: tr2,tr3,tr4,tr5]
__device__ unsigned g_done;              // gemm2 completion counter

// ---------------------------- helpers ---------------------------------------
__device__ __forceinline__ uint32_t smem_u32(const void* p) {
    uint32_t a;
    asm("{ .reg .u64 t; cvta.to.shared.u64 t, %1; cvt.u32.u64 %0, t; }" : "=r"(a) : "l"(p));
    return a;
}
#define CP16(dst, src) asm volatile("cp.async.cg.shared.global [%0], [%1], 16;" :: "r"((uint32_t)(dst)), "l"(src))
#define CP_COMMIT()    asm volatile("cp.async.commit_group;" ::: "memory")
#define CP_WAIT(n)     asm volatile("cp.async.wait_group %0;" :: "n"(n) : "memory")

#define MMA_F16(d, a, b) \
    asm volatile("mma.sync.aligned.m16n8k16.row.col.f32.f16.f16.f32 " \
        "{%0,%1,%2,%3},{%4,%5,%6,%7},{%8,%9},{%0,%1,%2,%3};" \
        : "+f"((d)[0]), "+f"((d)[1]), "+f"((d)[2]), "+f"((d)[3]) \
        : "r"((a)[0]), "r"((a)[1]), "r"((a)[2]), "r"((a)[3]), "r"((b)[0]), "r"((b)[1]))

#define LDSM4(r, addr) \
    asm volatile("ldmatrix.sync.aligned.m8n8.x4.shared.b16 {%0,%1,%2,%3}, [%4];" \
        : "=r"((r)[0]), "=r"((r)[1]), "=r"((r)[2]), "=r"((r)[3]) : "r"(addr))

#define LDSM4T(r, addr) \
    asm volatile("ldmatrix.sync.aligned.m8n8.x4.trans.shared.b16 {%0,%1,%2,%3}, [%4];" \
        : "=r"((r)[0]), "=r"((r)[1]), "=r"((r)[2]), "=r"((r)[3]) : "r"(addr))

// ---------------------------------------------------------------------------
// Conv via implicit GEMM on tensor cores (R14 version; also resets g_done).
// ---------------------------------------------------------------------------
#define CV_PADK 56
#define CV_P    0
#define CV_XS   57344
#define CV_WS   59040
#define CV_BS   60832
#define CV_SMEM 60896
#define CV_OS   18

__global__ void __launch_bounds__(256, 2) conv_kernel(const float* __restrict__ x,
                                                      const float* __restrict__ w,
                                                      const float* __restrict__ bias) {
    extern __shared__ char sm[];
    __half* P   = (__half*)(sm + CV_P);
    __half* xs  = (__half*)(sm + CV_XS);    // [21][40]
    __half* ws  = (__half*)(sm + CV_WS);    // [16][56]
    float*  bs  = (float*)(sm + CV_BS);
    const uint32_t sbase = smem_u32(sm);
    const int b  = blockIdx.z;
    const int by = blockIdx.y;
    const int bx = blockIdx.x;
    const int tid = threadIdx.x;
    const int lane = tid & 31, wp = tid >> 5;

    if (bx == 0 && by == 0 && b == 0 && tid == 0) g_done = 0;

    for (int i = tid; i < 21 * 37; i += 256) {
        int r = i / 37, c = i % 37;
        xs[r * 40 + c] = __float2half_rn(x[b * NN * NN + (by * 16 + r) * NN + bx * 32 + c]);
    }
    for (int i = tid; i < 16 * CV_PADK; i += 256) {
        int k = i % CV_PADK;
        ws[i] = (k < 36) ? __float2half_rn(w[(i / CV_PADK) * 36 + k]) : __float2half_rn(0.f);
    }
    if (tid < 16) bs[tid] = bias[tid];
    __syncthreads();

#pragma unroll
    for (int it = 0; it < 2; it++) {
        int o = it * 256 + tid;
        int r = o >> 5, c = o & 31;
        __half* Po = P + o * CV_PADK;
#pragma unroll
        for (int p = 0; p < 6; p++) {
            const __half* xr = xs + (r + p) * 40 + c;
#pragma unroll
            for (int j = 0; j < 3; j++)
                *(__half2*)&Po[p * 6 + 2 * j] = __halves2half2(xr[2 * j], xr[2 * j + 1]);
        }
#pragma unroll
        for (int j = 0; j < 6; j++)
            *(__half2*)&Po[36 + 2 * j] = __halves2half2(__float2half_rn(0.f), __float2half_rn(0.f));
    }
    __syncthreads();

    uint32_t bq[3][4];
    {
        uint32_t wOff = sbase + CV_WS
                      + (uint32_t)(((lane & 7) + ((lane >> 4) << 3)) * (CV_PADK * 2)
                      + ((lane >> 3) & 1) * 16);
#pragma unroll
        for (int k = 0; k < 3; k++) LDSM4(bq[k], wOff + (uint32_t)(k * 32));
    }

    const uint32_t aOff = sbase + CV_P
                        + (uint32_t)(((lane & 15) * CV_PADK + ((lane >> 4) << 3)) * 2)
                        + (uint32_t)(wp * 64 * CV_PADK * 2);
    float acc[4][2][4];
#pragma unroll
    for (int mi = 0; mi < 4; mi++)
#pragma unroll
        for (int ni = 0; ni < 2; ni++)
#pragma unroll
            for (int e = 0; e < 4; e++) acc[mi][ni][e] = 0.f;

#pragma unroll
    for (int mi = 0; mi < 4; mi++) {
#pragma unroll
        for (int k = 0; k < 3; k++) {
            uint32_t af[4];
            LDSM4(af, aOff + (uint32_t)(mi * 16 * CV_PADK * 2 + k * 32));
            MMA_F16(acc[mi][0], af, &bq[k][0]);
            MMA_F16(acc[mi][1], af, &bq[k][2]);
        }
    }
    __syncthreads();

    __half* outs = (__half*)(sm + CV_P);    // [512][CV_OS]
    const int fr = lane >> 2, fc = (lane & 3) * 2;
#pragma unroll
    for (int mi = 0; mi < 4; mi++) {
        int o = wp * 64 + mi * 16 + fr;
#pragma unroll
        for (int ni = 0; ni < 2; ni++) {
            int ch = ni * 8 + fc;
            float b0 = bs[ch], b1 = bs[ch + 1];
            *(__half2*)&outs[o * CV_OS + ch] =
                __halves2half2(__float2half_rn(acc[mi][ni][0] + b0),
                               __float2half_rn(acc[mi][ni][1] + b1));
            *(__half2*)&outs[(o + 8) * CV_OS + ch] =
                __halves2half2(__float2half_rn(acc[mi][ni][2] + b0),
                               __float2half_rn(acc[mi][ni][3] + b1));
        }
    }
    __syncthreads();

#pragma unroll
    for (int it = 0; it < 4; it++) {
        int u = it * 256 + tid;
        int ch = (u >> 2) & 15;
        int chunk = (u & 3) + ((u >> 6) << 2);
        int o0 = chunk * 8;
        int r = o0 >> 5, c0 = o0 & 31;
        __half tmp[8];
#pragma unroll
        for (int i = 0; i < 8; i++) tmp[i] = outs[(o0 + i) * CV_OS + ch];
        size_t dst = (size_t)(b * CHN + ch) * MAT + (size_t)(by * 16 + r) * MM + bx * 32 + c0;
        *(uint4*)&g_Ah[dst] = *(uint4*)tmp;
    }
}

// ---------------------------------------------------------------------------
// fp16 mma.sync GEMM, 128x128 tile, BK=32, 4-stage cp.async ring (R14 proven).
// IS2=1 additionally: last CTA (g_done) runs the trace-combine inline.
// ---------------------------------------------------------------------------
#define PADK    40
#define PADN    136
#define OFFB    10240u
#define SB      18944u
#define GEMM_SMEM 75776

__device__ __forceinline__ void load_stage(uint32_t st,
        const __half* __restrict__ Ah, const __half* __restrict__ Bsrc,
        int col0, int kb, int tid) {
#pragma unroll
    for (int it = 0; it < 2; ++it) {
        int u = it * 256 + tid;
        int rowA = u >> 2, segA = u & 3;
        uint32_t da = (uint32_t)(rowA * (PADK * 2) + segA * 16);
        CP16(st + da, Ah + rowA * MM + kb * 32 + segA * 8);
        int rowB = u >> 4, segB = u & 15;
        uint32_t db = (uint32_t)(rowB * (PADN * 2) + segB * 16);
        CP16(st + OFFB + db, Bsrc + (size_t)(kb * 32 + rowB) * MM + col0 + segB * 8);
    }
}

template <bool IS2>
__global__ void __launch_bounds__(256, 2) gemm_kernel(const float* __restrict__ coef,
                                                      float* __restrict__ out) {
    extern __shared__ char sm[];
    const uint32_t sbase = smem_u32(sm);
    const int tid  = threadIdx.x;
    const int lane = tid & 31;
    const int w    = tid >> 5;
    const int wm   = w >> 2;
    const int wn   = w & 3;
    const int bc   = blockIdx.z;
    const int row0 = blockIdx.y * 128;
    const int col0 = blockIdx.x * 128;
    const bool diag = (blockIdx.x == blockIdx.y);
    const size_t mbase = (size_t)bc * MAT;

    const __half* Ah = g_Ah + mbase + (size_t)row0 * MM;
    const __half* Bsrc = (IS2 ? g_B2h : g_Ah) + mbase;

    uint32_t aOff, bOff;
    if (!IS2) {
        aOff = (uint32_t)(((lane & 15) * PADK + ((lane >> 4) << 3)) * 2)
             + (uint32_t)(wm * 64 * PADK * 2);
        bOff = OFFB
             + (uint32_t)(((lane & 7) + ((lane >> 3) & 1) * 8) * (PADN * 2)
             + (wn * 32 + (lane >> 4) * 8) * 2);
    } else {
        aOff = OFFB
             + (uint32_t)(((lane & 7) + ((lane >> 4) << 3)) * (PADN * 2)
             + (wm * 64 + ((lane >> 3) & 1) * 8) * 2);
        bOff = (uint32_t)((wn * 32 + (lane & 7) + ((lane >> 4) << 3)) * (PADK * 2)
             + ((lane >> 3) & 1) * 16);
    }

    float acc[4][4][4];
#pragma unroll
    for (int mi = 0; mi < 4; mi++)
#pragma unroll
        for (int ni = 0; ni < 4; ni++)
#pragma unroll
            for (int e = 0; e < 4; e++) acc[mi][ni][e] = 0.f;

    load_stage(sbase + 0 * SB, Ah, Bsrc, col0, 0, tid); CP_COMMIT();
    load_stage(sbase + 1 * SB, Ah, Bsrc, col0, 1, tid); CP_COMMIT();
    load_stage(sbase + 2 * SB, Ah, Bsrc, col0, 2, tid); CP_COMMIT();

    for (int kb = 0; kb < 8; ++kb) {
        if (kb < 6) { CP_WAIT(2); }
        else if (kb == 6) { CP_WAIT(1); }
        else { CP_WAIT(0); }
        __syncthreads();
        if (kb + 3 < 8) {
            load_stage(sbase + (uint32_t)((kb + 3) & 3) * SB, Ah, Bsrc, col0, kb + 3, tid);
            CP_COMMIT();
        }

        const uint32_t st = sbase + (uint32_t)(kb & 3) * SB;

#pragma unroll
        for (int ks = 0; ks < 2; ++ks) {
            uint32_t af[4][4], bq[2][4];
            if (!IS2) {
#pragma unroll
                for (int mi = 0; mi < 4; mi++)
                    LDSM4(af[mi], st + aOff + (uint32_t)(mi * 16 * PADK * 2 + ks * 32));
#pragma unroll
                for (int q = 0; q < 2; q++)
                    LDSM4T(bq[q], st + bOff + (uint32_t)(ks * 16 * PADN * 2 + q * 16 * 2));
            } else {
#pragma unroll
                for (int mi = 0; mi < 4; mi++)
                    LDSM4T(af[mi], st + aOff + (uint32_t)(ks * 16 * PADN * 2 + mi * 16 * 2));
#pragma unroll
                for (int q = 0; q < 2; q++)
                    LDSM4(bq[q], st + bOff + (uint32_t)(q * 16 * PADK * 2 + ks * 32));
            }
#pragma unroll
            for (int mi = 0; mi < 4; mi++)
#pragma unroll
                for (int ni = 0; ni < 4; ni++)
                    MMA_F16(acc[mi][ni], af[mi], &bq[ni >> 1][(ni & 1) * 2]);
        }
    }
    __syncthreads();

    float p0 = 0.f, p2 = 0.f, p3 = 0.f;
    const int fr = lane >> 2;
    const int fc = (lane & 3) * 2;

    if (!IS2) {
#pragma unroll
        for (int mi = 0; mi < 4; mi++)
#pragma unroll
            for (int ni = 0; ni < 4; ni++) {
                int r = wm * 64 + mi * 16 + fr;
                int c = wn * 32 + ni * 8 + fc;
                float a0 = acc[mi][ni][0], a1 = acc[mi][ni][1];
                float a2 = acc[mi][ni][2], a3 = acc[mi][ni][3];
                size_t o = mbase + (size_t)(row0 + r) * MM + col0 + c;
                *(__half2*)&g_B2h[o] = __halves2half2(__float2half_rn(a0), __float2half_rn(a1));
                *(__half2*)&g_B2h[o + 8 * MM] = __halves2half2(__float2half_rn(a2), __float2half_rn(a3));
                if (diag) {
                    if (r == c)         p0 += a0;
                    if (r == c + 1)     p0 += a1;
                    if (r + 8 == c)     p0 += a2;
                    if (r + 8 == c + 1) p0 += a3;
                }
            }
    } else {
#pragma unroll
        for (int mi = 0; mi < 4; mi++)
#pragma unroll
            for (int ni = 0; ni < 4; ni++) {
                int j = wm * 64 + mi * 16 + fr;
                int i = wn * 32 + ni * 8 + fc;
                float a0 = acc[mi][ni][0], a1 = acc[mi][ni][1];
                float a2 = acc[mi][ni][2], a3 = acc[mi][ni][3];
                size_t o = mbase + (size_t)(col0 + j) * MM + row0 + i;
                float2 av1 = __half22float2(*(const __half2*)&g_Ah[o]);
                float2 bv1 = __half22float2(*(const __half2*)&g_B2h[o]);
                float2 av2 = __half22float2(*(const __half2*)&g_Ah[o + 8 * MM]);
                float2 bv2 = __half22float2(*(const __half2*)&g_B2h[o + 8 * MM]);
                p2 += a0 * av1.x + a1 * av1.y + a2 * av2.x + a3 * av2.y;
                p3 += a0 * bv1.x + a1 * bv1.y + a2 * bv2.x + a3 * bv2.y;
                if (diag) {
                    if (j == i)         p0 += a0;
                    if (j == i + 1)     p0 += a1;
                    if (j + 8 == i)     p0 += a2;
                    if (j + 8 == i + 1) p0 += a3;
                }
            }
    }

#pragma unroll
    for (int off = 16; off; off >>= 1) {
        p0 += __shfl_down_sync(0xFFFFFFFFu, p0, off);
        p2 += __shfl_down_sync(0xFFFFFFFFu, p2, off);
        p3 += __shfl_down_sync(0xFFFFFFFFu, p3, off);
    }
    float* red = (float*)sm;
    __syncthreads();
    if (lane == 0) {
        red[w * 3 + 0] = p0; red[w * 3 + 1] = p2; red[w * 3 + 2] = p3;
    }
    __syncthreads();
    if (tid == 0) {
        float s0 = 0.f, s2 = 0.f, s3 = 0.f;
        for (int q = 0; q < 8; q++) {
            s0 += red[q * 3]; s2 += red[q * 3 + 1]; s3 += red[q * 3 + 2];
        }
        int slot = (bc * 4 + (int)(blockIdx.y * 2 + blockIdx.x)) * 4;
        if (!IS2) g_part[slot + 0] = s0;
        else { g_part[slot + 1] = s0; g_part[slot + 2] = s2; g_part[slot + 3] = s3; }
    }

    // -------- fused finale: last gemm2 CTA combines traces -> out --------
    if (IS2) {
        __shared__ unsigned s_last;
        __threadfence();
        __syncthreads();
        if (tid == 0) s_last = atomicAdd(&g_done, 1u);
        __syncthreads();
        if (s_last == (unsigned)(NMAT * 4 - 1)) {
            __threadfence();
#pragma unroll
            for (int half = 0; half < 2; half++) {
                int b = (tid >> 4) + half * 16;
                int c = tid & 15;
                int bc2 = b * CHN + c;
                double tr[4];
#pragma unroll
                for (int k = 0; k < 4; k++) {
                    float s = 0.f;
#pragma unroll
                    for (int tile = 0; tile < 4; tile++) s += g_part[(bc2 * 4 + tile) * 4 + k];
                    tr[k] = (double)s;
                }
                double sum = 0.0;
#pragma unroll
                for (int i = 0; i < 4; i++) {
                    double p = tr[i];
                    double tp = p;
#pragma unroll
                    for (int jj = 0; jj < 4; jj++) {
                        double v = ldexp(tp, -16 * (i + jj + 1));
                        sum += (double)coef[c * 16 + i * 4 + jj] * v;
                        tp *= p;
                    }
                }
#pragma unroll
                for (int off = 8; off; off >>= 1)
                    sum += __shfl_down_sync(0xFFFFFFFFu, sum, off, 16);
                if (c == 0) out[b] = (float)sum;
            }
        }
    }
}

extern "C" void kernel_launch(void* const* d_in, const int* in_sizes, int n_in,
                              void* d_out, int out_size) {
    const float* x    = (const float*)d_in[0];
    const float* w    = (const float*)d_in[1];
    const float* bias = (const float*)d_in[2];
    const float* coef = (const float*)d_in[3];
    float* out = (float*)d_out;

    cudaFuncSetAttribute(conv_kernel, cudaFuncAttributeMaxDynamicSharedMemorySize, CV_SMEM);
    cudaFuncSetAttribute(gemm_kernel<false>, cudaFuncAttributeMaxDynamicSharedMemorySize, GEMM_SMEM);
    cudaFuncSetAttribute(gemm_kernel<true>,  cudaFuncAttributeMaxDynamicSharedMemorySize, GEMM_SMEM);

    conv_kernel<<<dim3(8, 16, BB), 256, CV_SMEM>>>(x, w, bias);
    gemm_kernel<false><<<dim3(2, 2, NMAT), 256, GEMM_SMEM>>>(coef, out);
    gemm_kernel<true> <<<dim3(2, 2, NMAT), 256, GEMM_SMEM>>>(coef, out);
}

// round 17
// speedup vs baseline: 1.0835x; 1.0199x over previous
#include <cuda_runtime.h>
#include <cuda_fp16.h>
#include <cstdint>

#define BB   32
#define CHN  16
#define NN   261
#define MM   256
#define MAT  (MM*MM)
#define NMAT (BB*CHN)

// ---------------- scratch (device globals; no allocs allowed) ----------------
__device__ __align__(256) __half g_Ah  [NMAT * MAT];   // feat fp16 (row-major)
__device__ __align__(256) __half g_B2h [NMAT * MAT];   // B2 row-major fp16
__device__ float g_part[NMAT * 4 * 4];   // [bc][tile 2x2][k: tr2,tr3,tr4,tr5]

// ---------------------------- helpers ---------------------------------------
__device__ __forceinline__ uint32_t smem_u32(const void* p) {
    uint32_t a;
    asm("{ .reg .u64 t; cvta.to.shared.u64 t, %1; cvt.u32.u64 %0, t; }" : "=r"(a) : "l"(p));
    return a;
}
#define CP16(dst, src) asm volatile("cp.async.cg.shared.global [%0], [%1], 16;" :: "r"((uint32_t)(dst)), "l"(src))
#define CP_COMMIT()    asm volatile("cp.async.commit_group;" ::: "memory")
#define CP_WAIT(n)     asm volatile("cp.async.wait_group %0;" :: "n"(n) : "memory")

#define MMA_F16(d, a, b) \
    asm volatile("mma.sync.aligned.m16n8k16.row.col.f32.f16.f16.f32 " \
        "{%0,%1,%2,%3},{%4,%5,%6,%7},{%8,%9},{%0,%1,%2,%3};" \
        : "+f"((d)[0]), "+f"((d)[1]), "+f"((d)[2]), "+f"((d)[3]) \
        : "r"((a)[0]), "r"((a)[1]), "r"((a)[2]), "r"((a)[3]), "r"((b)[0]), "r"((b)[1]))

#define LDSM4(r, addr) \
    asm volatile("ldmatrix.sync.aligned.m8n8.x4.shared.b16 {%0,%1,%2,%3}, [%4];" \
        : "=r"((r)[0]), "=r"((r)[1]), "=r"((r)[2]), "=r"((r)[3]) : "r"(addr))

#define LDSM4T(r, addr) \
    asm volatile("ldmatrix.sync.aligned.m8n8.x4.trans.shared.b16 {%0,%1,%2,%3}, [%4];" \
        : "=r"((r)[0]), "=r"((r)[1]), "=r"((r)[2]), "=r"((r)[3]) : "r"(addr))

// ---------------------------------------------------------------------------
// Conv via implicit GEMM on tensor cores (R14 layout; 3 CTAs/SM).
// ---------------------------------------------------------------------------
#define CV_PADK 56
#define CV_P    0
#define CV_XS   57344
#define CV_WS   59040
#define CV_BS   60832
#define CV_SMEM 60896
#define CV_OS   18

__global__ void __launch_bounds__(256, 3) conv_kernel(const float* __restrict__ x,
                                                      const float* __restrict__ w,
                                                      const float* __restrict__ bias) {
    extern __shared__ char sm[];
    __half* P   = (__half*)(sm + CV_P);
    __half* xs  = (__half*)(sm + CV_XS);    // [21][40]
    __half* ws  = (__half*)(sm + CV_WS);    // [16][56]
    float*  bs  = (float*)(sm + CV_BS);
    const uint32_t sbase = smem_u32(sm);
    const int b  = blockIdx.z;
    const int by = blockIdx.y;
    const int bx = blockIdx.x;
    const int tid = threadIdx.x;
    const int lane = tid & 31, wp = tid >> 5;

    for (int i = tid; i < 21 * 37; i += 256) {
        int r = i / 37, c = i % 37;
        xs[r * 40 + c] = __float2half_rn(x[b * NN * NN + (by * 16 + r) * NN + bx * 32 + c]);
    }
    for (int i = tid; i < 16 * CV_PADK; i += 256) {
        int k = i % CV_PADK;
        ws[i] = (k < 36) ? __float2half_rn(w[(i / CV_PADK) * 36 + k]) : __float2half_rn(0.f);
    }
    if (tid < 16) bs[tid] = bias[tid];
    __syncthreads();

#pragma unroll
    for (int it = 0; it < 2; it++) {
        int o = it * 256 + tid;
        int r = o >> 5, c = o & 31;
        __half* Po = P + o * CV_PADK;
#pragma unroll
        for (int p = 0; p < 6; p++) {
            const __half* xr = xs + (r + p) * 40 + c;
#pragma unroll
            for (int j = 0; j < 3; j++)
                *(__half2*)&Po[p * 6 + 2 * j] = __halves2half2(xr[2 * j], xr[2 * j + 1]);
        }
#pragma unroll
        for (int j = 0; j < 6; j++)
            *(__half2*)&Po[36 + 2 * j] = __halves2half2(__float2half_rn(0.f), __float2half_rn(0.f));
    }
    __syncthreads();

    uint32_t bq[3][4];
    {
        uint32_t wOff = sbase + CV_WS
                      + (uint32_t)(((lane & 7) + ((lane >> 4) << 3)) * (CV_PADK * 2)
                      + ((lane >> 3) & 1) * 16);
#pragma unroll
        for (int k = 0; k < 3; k++) LDSM4(bq[k], wOff + (uint32_t)(k * 32));
    }

    const uint32_t aOff = sbase + CV_P
                        + (uint32_t)(((lane & 15) * CV_PADK + ((lane >> 4) << 3)) * 2)
                        + (uint32_t)(wp * 64 * CV_PADK * 2);
    float acc[4][2][4];
#pragma unroll
    for (int mi = 0; mi < 4; mi++)
#pragma unroll
        for (int ni = 0; ni < 2; ni++)
#pragma unroll
            for (int e = 0; e < 4; e++) acc[mi][ni][e] = 0.f;

#pragma unroll
    for (int mi = 0; mi < 4; mi++) {
#pragma unroll
        for (int k = 0; k < 3; k++) {
            uint32_t af[4];
            LDSM4(af, aOff + (uint32_t)(mi * 16 * CV_PADK * 2 + k * 32));
            MMA_F16(acc[mi][0], af, &bq[k][0]);
            MMA_F16(acc[mi][1], af, &bq[k][2]);
        }
    }
    __syncthreads();

    __half* outs = (__half*)(sm + CV_P);    // [512][CV_OS]
    const int fr = lane >> 2, fc = (lane & 3) * 2;
#pragma unroll
    for (int mi = 0; mi < 4; mi++) {
        int o = wp * 64 + mi * 16 + fr;
#pragma unroll
        for (int ni = 0; ni < 2; ni++) {
            int ch = ni * 8 + fc;
            float b0 = bs[ch], b1 = bs[ch + 1];
            *(__half2*)&outs[o * CV_OS + ch] =
                __halves2half2(__float2half_rn(acc[mi][ni][0] + b0),
                               __float2half_rn(acc[mi][ni][1] + b1));
            *(__half2*)&outs[(o + 8) * CV_OS + ch] =
                __halves2half2(__float2half_rn(acc[mi][ni][2] + b0),
                               __float2half_rn(acc[mi][ni][3] + b1));
        }
    }
    __syncthreads();

#pragma unroll
    for (int it = 0; it < 4; it++) {
        int u = it * 256 + tid;
        int ch = (u >> 2) & 15;
        int chunk = (u & 3) + ((u >> 6) << 2);
        int o0 = chunk * 8;
        int r = o0 >> 5, c0 = o0 & 31;
        __half tmp[8];
#pragma unroll
        for (int i = 0; i < 8; i++) tmp[i] = outs[(o0 + i) * CV_OS + ch];
        size_t dst = (size_t)(b * CHN + ch) * MAT + (size_t)(by * 16 + r) * MM + bx * 32 + c0;
        *(uint4*)&g_Ah[dst] = *(uint4*)tmp;
    }
}

// ---------------------------------------------------------------------------
// fp16 mma.sync GEMM, 128x128 tile, BK=32, 4-stage cp.async ring (R14 proven).
// ---------------------------------------------------------------------------
#define PADK    40
#define PADN    136
#define OFFB    10240u
#define SB      18944u
#define GEMM_SMEM 75776

__device__ __forceinline__ void load_stage(uint32_t st,
        const __half* __restrict__ Ah, const __half* __restrict__ Bsrc,
        int col0, int kb, int tid) {
#pragma unroll
    for (int it = 0; it < 2; ++it) {
        int u = it * 256 + tid;
        int rowA = u >> 2, segA = u & 3;
        uint32_t da = (uint32_t)(rowA * (PADK * 2) + segA * 16);
        CP16(st + da, Ah + rowA * MM + kb * 32 + segA * 8);
        int rowB = u >> 4, segB = u & 15;
        uint32_t db = (uint32_t)(rowB * (PADN * 2) + segB * 16);
        CP16(st + OFFB + db, Bsrc + (size_t)(kb * 32 + rowB) * MM + col0 + segB * 8);
    }
}

template <bool IS2>
__global__ void __launch_bounds__(256, 2) gemm_kernel() {
    extern __shared__ char sm[];
    const uint32_t sbase = smem_u32(sm);
    const int tid  = threadIdx.x;
    const int lane = tid & 31;
    const int w    = tid >> 5;
    const int wm   = w >> 2;
    const int wn   = w & 3;
    const int bc   = blockIdx.z;
    const int row0 = blockIdx.y * 128;
    const int col0 = blockIdx.x * 128;
    const bool diag = (blockIdx.x == blockIdx.y);
    const size_t mbase = (size_t)bc * MAT;

    const __half* Ah = g_Ah + mbase + (size_t)row0 * MM;
    const __half* Bsrc = (IS2 ? g_B2h : g_Ah) + mbase;

    uint32_t aOff, bOff;
    if (!IS2) {
        aOff = (uint32_t)(((lane & 15) * PADK + ((lane >> 4) << 3)) * 2)
             + (uint32_t)(wm * 64 * PADK * 2);
        bOff = OFFB
             + (uint32_t)(((lane & 7) + ((lane >> 3) & 1) * 8) * (PADN * 2)
             + (wn * 32 + (lane >> 4) * 8) * 2);
    } else {
        aOff = OFFB
             + (uint32_t)(((lane & 7) + ((lane >> 4) << 3)) * (PADN * 2)
             + (wm * 64 + ((lane >> 3) & 1) * 8) * 2);
        bOff = (uint32_t)((wn * 32 + (lane & 7) + ((lane >> 4) << 3)) * (PADK * 2)
             + ((lane >> 3) & 1) * 16);
    }

    float acc[4][4][4];
#pragma unroll
    for (int mi = 0; mi < 4; mi++)
#pragma unroll
        for (int ni = 0; ni < 4; ni++)
#pragma unroll
            for (int e = 0; e < 4; e++) acc[mi][ni][e] = 0.f;

    load_stage(sbase + 0 * SB, Ah, Bsrc, col0, 0, tid); CP_COMMIT();
    load_stage(sbase + 1 * SB, Ah, Bsrc, col0, 1, tid); CP_COMMIT();
    load_stage(sbase + 2 * SB, Ah, Bsrc, col0, 2, tid); CP_COMMIT();

    for (int kb = 0; kb < 8; ++kb) {
        if (kb < 6) { CP_WAIT(2); }
        else if (kb == 6) { CP_WAIT(1); }
        else { CP_WAIT(0); }
        __syncthreads();
        if (kb + 3 < 8) {
            load_stage(sbase + (uint32_t)((kb + 3) & 3) * SB, Ah, Bsrc, col0, kb + 3, tid);
            CP_COMMIT();
        }

        const uint32_t st = sbase + (uint32_t)(kb & 3) * SB;

#pragma unroll
        for (int ks = 0; ks < 2; ++ks) {
            uint32_t af[4][4], bq[2][4];
            if (!IS2) {
#pragma unroll
                for (int mi = 0; mi < 4; mi++)
                    LDSM4(af[mi], st + aOff + (uint32_t)(mi * 16 * PADK * 2 + ks * 32));
#pragma unroll
                for (int q = 0; q < 2; q++)
                    LDSM4T(bq[q], st + bOff + (uint32_t)(ks * 16 * PADN * 2 + q * 16 * 2));
            } else {
#pragma unroll
                for (int mi = 0; mi < 4; mi++)
                    LDSM4T(af[mi], st + aOff + (uint32_t)(ks * 16 * PADN * 2 + mi * 16 * 2));
#pragma unroll
                for (int q = 0; q < 2; q++)
                    LDSM4(bq[q], st + bOff + (uint32_t)(q * 16 * PADK * 2 + ks * 32));
            }
#pragma unroll
            for (int mi = 0; mi < 4; mi++)
#pragma unroll
                for (int ni = 0; ni < 4; ni++)
                    MMA_F16(acc[mi][ni], af[mi], &bq[ni >> 1][(ni & 1) * 2]);
        }
    }
    __syncthreads();

    float p0 = 0.f, p2 = 0.f, p3 = 0.f;
    const int fr = lane >> 2;
    const int fc = (lane & 3) * 2;

    if (!IS2) {
#pragma unroll
        for (int mi = 0; mi < 4; mi++)
#pragma unroll
            for (int ni = 0; ni < 4; ni++) {
                int r = wm * 64 + mi * 16 + fr;
                int c = wn * 32 + ni * 8 + fc;
                float a0 = acc[mi][ni][0], a1 = acc[mi][ni][1];
                float a2 = acc[mi][ni][2], a3 = acc[mi][ni][3];
                size_t o = mbase + (size_t)(row0 + r) * MM + col0 + c;
                *(__half2*)&g_B2h[o] = __halves2half2(__float2half_rn(a0), __float2half_rn(a1));
                *(__half2*)&g_B2h[o + 8 * MM] = __halves2half2(__float2half_rn(a2), __float2half_rn(a3));
                if (diag) {
                    if (r == c)         p0 += a0;
                    if (r == c + 1)     p0 += a1;
                    if (r + 8 == c)     p0 += a2;
                    if (r + 8 == c + 1) p0 += a3;
                }
            }
    } else {
#pragma unroll
        for (int mi = 0; mi < 4; mi++)
#pragma unroll
            for (int ni = 0; ni < 4; ni++) {
                int j = wm * 64 + mi * 16 + fr;
                int i = wn * 32 + ni * 8 + fc;
                float a0 = acc[mi][ni][0], a1 = acc[mi][ni][1];
                float a2 = acc[mi][ni][2], a3 = acc[mi][ni][3];
                size_t o = mbase + (size_t)(col0 + j) * MM + row0 + i;
                float2 av1 = __half22float2(*(const __half2*)&g_Ah[o]);
                float2 bv1 = __half22float2(*(const __half2*)&g_B2h[o]);
                float2 av2 = __half22float2(*(const __half2*)&g_Ah[o + 8 * MM]);
                float2 bv2 = __half22float2(*(const __half2*)&g_B2h[o + 8 * MM]);
                p2 += a0 * av1.x + a1 * av1.y + a2 * av2.x + a3 * av2.y;
                p3 += a0 * bv1.x + a1 * bv1.y + a2 * bv2.x + a3 * bv2.y;
                if (diag) {
                    if (j == i)         p0 += a0;
                    if (j == i + 1)     p0 += a1;
                    if (j + 8 == i)     p0 += a2;
                    if (j + 8 == i + 1) p0 += a3;
                }
            }
    }

#pragma unroll
    for (int off = 16; off; off >>= 1) {
        p0 += __shfl_down_sync(0xFFFFFFFFu, p0, off);
        p2 += __shfl_down_sync(0xFFFFFFFFu, p2, off);
        p3 += __shfl_down_sync(0xFFFFFFFFu, p3, off);
    }
    float* red = (float*)sm;
    __syncthreads();
    if (lane == 0) {
        red[w * 3 + 0] = p0; red[w * 3 + 1] = p2; red[w * 3 + 2] = p3;
    }
    __syncthreads();
    if (tid == 0) {
        float s0 = 0.f, s2 = 0.f, s3 = 0.f;
        for (int q = 0; q < 8; q++) {
            s0 += red[q * 3]; s2 += red[q * 3 + 1]; s3 += red[q * 3 + 2];
        }
        int slot = (bc * 4 + (int)(blockIdx.y * 2 + blockIdx.x)) * 4;
        if (!IS2) g_part[slot + 0] = s0;
        else { g_part[slot + 1] = s0; g_part[slot + 2] = s2; g_part[slot + 3] = s3; }
    }
}

// ---------------------------------------------------------------------------
// Combine: out[b] = sum coef[c,i,j] * tr_{i+2}^(j+1) / 65536^(i+j+1)
// ---------------------------------------------------------------------------
__global__ void __launch_bounds__(512) final_kernel(const float* __restrict__ coef,
                                                    float* __restrict__ out) {
    int t = threadIdx.x;
    int b = t >> 4, c = t & 15;
    int bc = b * CHN + c;
    double tr[4];
#pragma unroll
    for (int k = 0; k < 4; k++) {
        float s = 0.f;
#pragma unroll
        for (int tile = 0; tile < 4; tile++) s += g_part[(bc * 4 + tile) * 4 + k];
        tr[k] = (double)s;
    }
    double sum = 0.0;
#pragma unroll
    for (int i = 0; i < 4; i++) {
        double p = tr[i];
        double tp = p;
#pragma unroll
        for (int j = 0; j < 4; j++) {
            double v = ldexp(tp, -16 * (i + j + 1));
            sum += (double)coef[c * 16 + i * 4 + j] * v;
            tp *= p;
        }
    }
#pragma unroll
    for (int off = 8; off; off >>= 1)
        sum += __shfl_down_sync(0xFFFFFFFFu, sum, off, 16);
    if (c == 0) out[b] = (float)sum;
}

extern "C" void kernel_launch(void* const* d_in, const int* in_sizes, int n_in,
                              void* d_out, int out_size) {
    const float* x    = (const float*)d_in[0];
    const float* w    = (const float*)d_in[1];
    const float* bias = (const float*)d_in[2];
    const float* coef = (const float*)d_in[3];
    float* out = (float*)d_out;

    cudaFuncSetAttribute(conv_kernel, cudaFuncAttributeMaxDynamicSharedMemorySize, CV_SMEM);
    cudaFuncSetAttribute(gemm_kernel<false>, cudaFuncAttributeMaxDynamicSharedMemorySize, GEMM_SMEM);
    cudaFuncSetAttribute(gemm_kernel<true>,  cudaFuncAttributeMaxDynamicSharedMemorySize, GEMM_SMEM);

    conv_kernel<<<dim3(8, 16, BB), 256, CV_SMEM>>>(x, w, bias);
    gemm_kernel<false><<<dim3(2, 2, NMAT), 256, GEMM_SMEM>>>();
    gemm_kernel<true> <<<dim3(2, 2, NMAT), 256, GEMM_SMEM>>>();
    final_kernel<<<1, 512>>>(coef, out);
}